// round 11
// baseline (speedup 1.0000x reference)
#include <cuda_runtime.h>
#include <cuda.h>
#include <cuda_bf16.h>

#define NN 8192
#define L2E 1.4426950408889634f
#define SPLIT 4
#define TILES 32

// smem layout (bytes) for k_attn
#define ADJ_OFF 0            // 2 x 32768
#define K_OFF   65536        // 2 x 8192
#define V_OFF   81920        // 2 x 8192
#define STK_OFF 98304        // 2 x 256
#define MB_OFF  98816        // 2 x 8
#define SMEM_SZ 98944

// k_prep dynamic smem: sA (4KB) + 3 x 16KB weight buffers
#define PREP_SMEM 53248

// Scratch (no allocation allowed)
__device__ float g_h[NN * 64];
__device__ float g_aggp[SPLIT][NN * 64];
__device__ float g_denp[SPLIT][NN];
__device__ __nv_bfloat16 g_qb[NN * 64];
__device__ __nv_bfloat16 g_kb[NN * 64];
__device__ __nv_bfloat16 g_mb[NN * 64];
__device__ float g_stk[NN];

// ---------------------------------------------------------------------------
__device__ __forceinline__ unsigned s2u(const void* p) {
    return (unsigned)__cvta_generic_to_shared(p);
}
__device__ __forceinline__ void cpa16(unsigned d, const void* s) {
    asm volatile("cp.async.cg.shared.global [%0],[%1],16;" :: "r"(d), "l"(s));
}
__device__ __forceinline__ void cpa4(unsigned d, const void* s) {
    asm volatile("cp.async.ca.shared.global [%0],[%1],4;" :: "r"(d), "l"(s));
}
__device__ __forceinline__ void cpcommit() { asm volatile("cp.async.commit_group;"); }
template <int N> __device__ __forceinline__ void cpwait() {
    asm volatile("cp.async.wait_group %0;" :: "n"(N));
}
__device__ __forceinline__ void mb_init(unsigned a, unsigned c) {
    asm volatile("mbarrier.init.shared.b64 [%0], %1;" :: "r"(a), "r"(c));
}
__device__ __forceinline__ void mb_exptx(unsigned a, unsigned b) {
    asm volatile("mbarrier.arrive.expect_tx.shared.b64 _, [%0], %1;" :: "r"(a), "r"(b) : "memory");
}
__device__ __forceinline__ void mb_wait(unsigned a, unsigned ph) {
    asm volatile(
        "{\n\t.reg .pred P;\n\t"
        "W%=:\n\t"
        "mbarrier.try_wait.parity.acquire.cta.shared::cta.b64 P, [%0], %1, 0x989680;\n\t"
        "@!P bra W%=;\n\t}"
        :: "r"(a), "r"(ph) : "memory");
}
__device__ __forceinline__ void tma2d(unsigned long long m, unsigned dst, int x, int y, unsigned mb) {
    asm volatile(
        "cp.async.bulk.tensor.2d.shared::cta.global.tile.mbarrier::complete_tx::bytes "
        "[%0], [%1, {%2, %3}], [%4];"
        :: "r"(dst), "l"(m), "r"(x), "r"(y), "r"(mb) : "memory");
}
__device__ __forceinline__ void ldm4(unsigned r[4], unsigned a) {
    asm volatile("ldmatrix.sync.aligned.m8n8.x4.shared.b16 {%0,%1,%2,%3}, [%4];"
                 : "=r"(r[0]), "=r"(r[1]), "=r"(r[2]), "=r"(r[3]) : "r"(a));
}
__device__ __forceinline__ void ldm4t(unsigned r[4], unsigned a) {
    asm volatile("ldmatrix.sync.aligned.m8n8.x4.trans.shared.b16 {%0,%1,%2,%3}, [%4];"
                 : "=r"(r[0]), "=r"(r[1]), "=r"(r[2]), "=r"(r[3]) : "r"(a));
}
__device__ __forceinline__ void mma16(float d[4], const unsigned a[4], unsigned b0, unsigned b1) {
    asm volatile("mma.sync.aligned.m16n8k16.row.col.f32.bf16.bf16.f32 "
                 "{%0,%1,%2,%3}, {%4,%5,%6,%7}, {%8,%9}, {%0,%1,%2,%3};"
                 : "+f"(d[0]), "+f"(d[1]), "+f"(d[2]), "+f"(d[3])
                 : "r"(a[0]), "r"(a[1]), "r"(a[2]), "r"(a[3]), "r"(b0), "r"(b1));
}
__device__ __forceinline__ unsigned long long pk2(float x) {
    unsigned long long r;
    asm("mov.b64 %0, {%1, %1};" : "=l"(r) : "f"(x));
    return r;
}

// Packed pair: P = adj * 2^(S + crow*st); accumulates packed den; returns bf16x2.
__device__ __forceinline__ unsigned pexp2(
    float s0, float s1, float stx, float sty, float crow, float a0, float a1,
    unsigned long long MAG2, unsigned long long NMAG2, unsigned long long NEG12,
    unsigned long long C4, unsigned long long C3, unsigned long long C2,
    unsigned long long C1, unsigned long long ONE2,
    unsigned long long& den2) {
    unsigned out;
    asm(
        "{\n\t"
        ".reg .b64 S2, st2, cr2, ad2, t2, rb2, r2, f2, p2, sc2;\n\t"
        ".reg .b32 il, ih;\n\t"
        ".reg .f32 sl, sh, pl, ph;\n\t"
        "mov.b64 S2, {%2, %3};\n\t"
        "mov.b64 st2, {%4, %5};\n\t"
        "mov.b64 cr2, {%6, %6};\n\t"
        "mov.b64 ad2, {%7, %8};\n\t"
        "fma.rn.f32x2 t2, cr2, st2, S2;\n\t"
        "add.rn.f32x2 rb2, t2, %9;\n\t"
        "add.rn.f32x2 r2, rb2, %10;\n\t"
        "fma.rn.f32x2 f2, r2, %11, t2;\n\t"
        "fma.rn.f32x2 p2, f2, %12, %13;\n\t"
        "fma.rn.f32x2 p2, f2, p2, %14;\n\t"
        "fma.rn.f32x2 p2, f2, p2, %15;\n\t"
        "fma.rn.f32x2 p2, f2, p2, %16;\n\t"
        "mov.b64 {il, ih}, rb2;\n\t"
        "shl.b32 il, il, 23;\n\t"
        "shl.b32 ih, ih, 23;\n\t"
        "add.s32 il, il, 0x3f800000;\n\t"
        "add.s32 ih, ih, 0x3f800000;\n\t"
        "mov.b32 sl, il;\n\t"
        "mov.b32 sh, ih;\n\t"
        "mov.b64 sc2, {sl, sh};\n\t"
        "mul.rn.f32x2 sc2, sc2, ad2;\n\t"
        "mul.rn.f32x2 p2, p2, sc2;\n\t"
        "add.rn.f32x2 %1, %1, p2;\n\t"
        "mov.b64 {pl, ph}, p2;\n\t"
        "cvt.rn.bf16x2.f32 %0, ph, pl;\n\t"
        "}"
        : "=r"(out), "+l"(den2)
        : "f"(s0), "f"(s1), "f"(stx), "f"(sty), "f"(crow), "f"(a0), "f"(a1),
          "l"(MAG2), "l"(NMAG2), "l"(NEG12), "l"(C4), "l"(C3), "l"(C2),
          "l"(C1), "l"(ONE2));
    return out;
}

// ---------------------------------------------------------------------------
__device__ __forceinline__ void store_bf16_row4(__nv_bfloat16* dst, const float* a, float s) {
    __nv_bfloat162 v01, v23;
    v01.x = __float2bfloat16(a[0] * s); v01.y = __float2bfloat16(a[1] * s);
    v23.x = __float2bfloat16(a[2] * s); v23.y = __float2bfloat16(a[3] * s);
    ((__nv_bfloat162*)dst)[0] = v01;
    ((__nv_bfloat162*)dst)[1] = v23;
}

// K1: BM=16, grid 512 (~3.5 CTAs/SM). Fused q/k/m pass; weights via cp.async.
__global__ __launch_bounds__(256) void k_prep(
    const float* __restrict__ nf, const float* __restrict__ tc,
    const float* __restrict__ w1, const float* __restrict__ b1,
    const float* __restrict__ w2, const float* __restrict__ b2,
    const float* __restrict__ wq, const float* __restrict__ bq,
    const float* __restrict__ wk, const float* __restrict__ bk,
    const float* __restrict__ wm, const float* __restrict__ bm,
    const float* __restrict__ wg, const float* __restrict__ bg) {
    extern __shared__ __align__(16) float dsmf[];
    float* sA  = dsmf;          // 16x64
    float* sW0 = dsmf + 1024;   // w2, then wm
    float* sW1 = dsmf + 5120;   // wq
    float* sW2 = dsmf + 9216;   // wk
    __shared__ float sG[65];

    const int tid = threadIdx.x;
    const int row = tid >> 4;            // 0..15
    const int c0 = (tid & 15) << 2;
    const int q0 = blockIdx.x * 16;
    const float tc0 = tc[0], tc1 = tc[1];

    // async weight prefetch: group A = w2 ; group B = wq, wk
    {
        unsigned d = s2u(sW0) + tid * 16;
        const char* s = (const char*)w2 + tid * 16;
#pragma unroll
        for (int i = 0; i < 4; i++) cpa16(d + i * 4096, s + i * 4096);
        cpcommit();
        unsigned d1 = s2u(sW1) + tid * 16;
        const char* s1 = (const char*)wq + tid * 16;
        unsigned d2 = s2u(sW2) + tid * 16;
        const char* s2 = (const char*)wk + tid * 16;
#pragma unroll
        for (int i = 0; i < 4; i++) { cpa16(d1 + i * 4096, s1 + i * 4096); cpa16(d2 + i * 4096, s2 + i * 4096); }
        cpcommit();
    }

    if (tid < 16) g_stk[q0 + tid] = nf[(q0 + tid) * 3 + 2];
    if (tid < 64) {
        float v = fmaf(tc0, wg[tid], fmaf(tc1, wg[64 + tid], bg[tid]));
        sG[tid] = 1.0f / (1.0f + __expf(-v));
    }

    // Stage 0: a = relu(x @ w1 + b1) -> sA
    {
        float x0 = nf[(q0 + row) * 3 + 0];
        float x1 = nf[(q0 + row) * 3 + 1];
        float x2 = nf[(q0 + row) * 3 + 2];
#pragma unroll
        for (int c = 0; c < 4; c++) {
            int col = c0 + c;
            float bb = fmaf(tc0, w1[192 + col], fmaf(tc1, w1[256 + col], b1[col]));
            float a = fmaf(x0, w1[col], fmaf(x1, w1[64 + col], fmaf(x2, w1[128 + col], bb)));
            sA[row * 64 + col] = fmaxf(a, 0.0f);
        }
    }
    cpwait<1>();          // w2 landed
    __syncthreads();
    if (tid == 0) {
        float s = 0.0f;
#pragma unroll 8
        for (int i = 0; i < 64; i++) s += sG[i];
        sG[64] = s * (1.0f / 64.0f) * 0.125f * L2E;   // gate/8 * log2e
    }

    // Stage 1: h = a @ w2 + b2
    float acc[4];
    {
        float4 bb = *(const float4*)&b2[c0];
        acc[0] = bb.x; acc[1] = bb.y; acc[2] = bb.z; acc[3] = bb.w;
#pragma unroll 8
        for (int j = 0; j < 64; j++) {
            float4 wv = *(const float4*)&sW0[j * 64 + c0];
            float av = sA[row * 64 + j];
            acc[0] = fmaf(av, wv.x, acc[0]);
            acc[1] = fmaf(av, wv.y, acc[1]);
            acc[2] = fmaf(av, wv.z, acc[2]);
            acc[3] = fmaf(av, wv.w, acc[3]);
        }
    }
    __syncthreads();      // all reads of sA / sW0 done

    // overwrite sA with h; prefetch wm into sW0
    {
        unsigned d = s2u(sW0) + tid * 16;
        const char* s = (const char*)wm + tid * 16;
#pragma unroll
        for (int i = 0; i < 4; i++) cpa16(d + i * 4096, s + i * 4096);
        cpcommit();
    }
    {
        float4 hv = make_float4(acc[0], acc[1], acc[2], acc[3]);
        *(float4*)&sA[row * 64 + c0] = hv;
        *(float4*)&g_h[(q0 + row) * 64 + c0] = hv;
    }
    cpwait<0>();          // wq, wk, wm all landed
    __syncthreads();

    // Stage 2: fused q/k/m GEMM — one pass over sA
    float aq[4], ak[4], am[4];
    {
        float4 bbq = *(const float4*)&bq[c0];
        float4 bbk = *(const float4*)&bk[c0];
        float4 bbm = *(const float4*)&bm[c0];
        aq[0] = bbq.x; aq[1] = bbq.y; aq[2] = bbq.z; aq[3] = bbq.w;
        ak[0] = bbk.x; ak[1] = bbk.y; ak[2] = bbk.z; ak[3] = bbk.w;
        am[0] = bbm.x; am[1] = bbm.y; am[2] = bbm.z; am[3] = bbm.w;
    }
#pragma unroll 4
    for (int j = 0; j < 64; j++) {
        float av = sA[row * 64 + j];
        float4 wvq = *(const float4*)&sW1[j * 64 + c0];
        float4 wvk = *(const float4*)&sW2[j * 64 + c0];
        float4 wvm = *(const float4*)&sW0[j * 64 + c0];
        aq[0] = fmaf(av, wvq.x, aq[0]); aq[1] = fmaf(av, wvq.y, aq[1]);
        aq[2] = fmaf(av, wvq.z, aq[2]); aq[3] = fmaf(av, wvq.w, aq[3]);
        ak[0] = fmaf(av, wvk.x, ak[0]); ak[1] = fmaf(av, wvk.y, ak[1]);
        ak[2] = fmaf(av, wvk.z, ak[2]); ak[3] = fmaf(av, wvk.w, ak[3]);
        am[0] = fmaf(av, wvm.x, am[0]); am[1] = fmaf(av, wvm.y, am[1]);
        am[2] = fmaf(av, wvm.z, am[2]); am[3] = fmaf(av, wvm.w, am[3]);
    }
    {
        float qs = sG[64];
        store_bf16_row4(&g_qb[(q0 + row) * 64 + c0], aq, qs);
        store_bf16_row4(&g_kb[(q0 + row) * 64 + c0], ak, 1.0f);
        store_bf16_row4(&g_mb[(q0 + row) * 64 + c0], am, 1.0f);
    }
}

// ---------------------------------------------------------------------------
// K2: flash attention. BM=128, BN=64, split-KV x4 (32 tiles). adj AND K/V via
// TMA on shared mbarriers; only stk on cp.async. Register-resident P.
__global__ __launch_bounds__(256) void k_attn(const __grid_constant__ CUtensorMap tmA,
                                              const __grid_constant__ CUtensorMap tmK,
                                              const __grid_constant__ CUtensorMap tmV,
                                              const float* __restrict__ tc,
                                              const float* __restrict__ sb) {
    extern __shared__ __align__(128) char dsm[];
    const unsigned su = s2u(dsm);
    const int tid = threadIdx.x;
    const int lane = tid & 31;
    const int wr = tid >> 5;
    const int r = lane >> 2;
    const int qd = lane & 3;
    const int c2 = qd << 1;
    const int qi = blockIdx.x >> 2;
    const int sp = blockIdx.x & 3;
    const int q0 = qi * 128;
    const int kvb = sp * 2048;
    const int gr = q0 + wr * 16 + r;
    const unsigned mbu = su + MB_OFF;

    if (tid == 0) { mb_init(mbu, 1); mb_init(mbu + 8, 1); }
    __syncthreads();

    const unsigned long long tA = (unsigned long long)&tmA;
    const unsigned long long tK = (unsigned long long)&tmK;
    const unsigned long long tV = (unsigned long long)&tmV;

#define ISSUE_TMA(T, B)                                                           \
    if (tid == 0) {                                                               \
        mb_exptx(mbu + 8 * (B), 49152);                                           \
        int x = kvb + (T) * 64;                                                   \
        tma2d(tA, su + ADJ_OFF + (B) * 32768,         x,      q0, mbu + 8 * (B)); \
        tma2d(tA, su + ADJ_OFF + (B) * 32768 + 16384, x + 32, q0, mbu + 8 * (B)); \
        tma2d(tK, su + K_OFF + (B) * 8192, 0, x, mbu + 8 * (B));                  \
        tma2d(tV, su + V_OFF + (B) * 8192, 0, x, mbu + 8 * (B));                  \
    }
#define STAGE_STK(T, B)                                                           \
    if (tid < 64) cpa4(su + STK_OFF + (B) * 256 + tid * 4, g_stk + kvb + (T) * 64 + tid);

    ISSUE_TMA(0, 0);
    ISSUE_TMA(1, 1);
    STAGE_STK(0, 0); cpcommit();
    STAGE_STK(1, 1); cpcommit();

    // Q fragments in registers
    unsigned qf[4][4];
#pragma unroll
    for (int kk = 0; kk < 4; kk++) {
        const __nv_bfloat16* qp = g_qb + (size_t)gr * 64 + kk * 16 + c2;
        qf[kk][0] = *(const unsigned*)qp;
        qf[kk][1] = *(const unsigned*)(qp + 512);
        qf[kk][2] = *(const unsigned*)(qp + 8);
        qf[kk][3] = *(const unsigned*)(qp + 520);
    }
    const float sbl = sb[0] * (1.0f - tc[0]) * L2E;
    const float crow0 = sbl * g_stk[gr];
    const float crow1 = sbl * g_stk[gr + 8];

    // packed constants (warp-uniform -> UR promotion)
    const unsigned long long MAG2 = pk2(12582912.0f);
    const unsigned long long NMAG2 = pk2(-12582912.0f);
    const unsigned long long NEG12 = pk2(-1.0f);
    const unsigned long long C4 = pk2(0.0096181291f);
    const unsigned long long C3 = pk2(0.0555041087f);
    const unsigned long long C2 = pk2(0.2402265070f);
    const unsigned long long C1 = pk2(0.6931471806f);
    const unsigned long long ONE2 = pk2(1.0f);

    // lane-constant smem addressing
    const unsigned swz = 16u * (lane & 7);
    const unsigned lrowK = (((lane >> 4) & 1) << 3) + (lane & 7);
    const unsigned lrowV = (((lane >> 3) & 1) << 3) + (lane & 7);
    const unsigned kc16 = ((lane >> 3) & 1) << 4;
    const unsigned vc16 = ((lane >> 4) & 1) << 4;
    unsigned kcol[4], vcol[4];
#pragma unroll
    for (int i = 0; i < 4; i++) {
        kcol[i] = ((unsigned)(i << 5) + kc16) ^ swz;
        vcol[i] = ((unsigned)(i << 5) + vc16) ^ swz;
    }
    const unsigned arow128 = (unsigned)(wr * 16 + r) << 7;
    const unsigned acb = 8u * qd;
    const unsigned aswz = 16u * r;

    float Ot[8][4];
#pragma unroll
    for (int n = 0; n < 8; n++) { Ot[n][0] = Ot[n][1] = Ot[n][2] = Ot[n][3] = 0.f; }
    unsigned long long den0_2 = 0ull, den1_2 = 0ull;

    for (int t = 0; t < TILES; t++) {
        const int b = t & 1;
        mb_wait(mbu + 8 * b, (t >> 1) & 1);
        cpwait<1>();
        __syncthreads();

        const unsigned kbase = su + K_OFF + b * 8192;
        const unsigned vbase = su + V_OFF + b * 8192;
        const char* adjb = dsm + b * 32768;
        const float* stkb = (const float*)(dsm + STK_OFF + b * 256);

        // S = Q @ K^T
        float S[8][4];
#pragma unroll
        for (int n = 0; n < 8; n++) { S[n][0] = S[n][1] = S[n][2] = S[n][3] = 0.f; }
#pragma unroll
        for (int jp = 0; jp < 4; jp++) {
            const unsigned rb = (unsigned)(16 * jp + lrowK) << 7;
#pragma unroll
            for (int kk = 0; kk < 4; kk++) {
                unsigned kf[4];
                ldm4(kf, kbase + rb + kcol[kk]);
                mma16(S[2 * jp],     qf[kk], kf[0], kf[1]);
                mma16(S[2 * jp + 1], qf[kk], kf[2], kf[3]);
            }
        }

        // interleaved pointwise + P@V, per k-chunk of 16 kv
#pragma unroll
        for (int kk = 0; kk < 4; kk++) {
            unsigned pa[4];
#pragma unroll
            for (int u = 0; u < 2; u++) {
                const int n = 2 * kk + u;
                float2 st = *(const float2*)(stkb + n * 8 + c2);
                unsigned ao = ((unsigned)(n >> 2) << 14) + arow128 +
                              ((acb + ((unsigned)(n & 3) << 5)) ^ aswz);
                float2 ad0 = *(const float2*)(adjb + ao);
                float2 ad1 = *(const float2*)(adjb + ao + 1024);
                pa[2 * u]     = pexp2(S[n][0], S[n][1], st.x, st.y, crow0, ad0.x, ad0.y,
                                      MAG2, NMAG2, NEG12, C4, C3, C2, C1, ONE2, den0_2);
                pa[2 * u + 1] = pexp2(S[n][2], S[n][3], st.x, st.y, crow1, ad1.x, ad1.y,
                                      MAG2, NMAG2, NEG12, C4, C3, C2, C1, ONE2, den1_2);
            }
#pragma unroll
            for (int dp = 0; dp < 4; dp++) {
                unsigned vf[4];
                ldm4t(vf, vbase + ((unsigned)(16 * kk + lrowV) << 7) + vcol[dp]);
                mma16(Ot[2 * dp],     pa, vf[0], vf[1]);
                mma16(Ot[2 * dp + 1], pa, vf[2], vf[3]);
            }
        }
        __syncthreads();

        if (t + 2 < TILES) {
            ISSUE_TMA(t + 2, b);
            STAGE_STK(t + 2, b);
        }
        cpcommit();
    }

    // unpack packed dens, reduce across quad, write partials
    float d0l, d0h, d1l, d1h;
    asm("mov.b64 {%0, %1}, %2;" : "=f"(d0l), "=f"(d0h) : "l"(den0_2));
    asm("mov.b64 {%0, %1}, %2;" : "=f"(d1l), "=f"(d1h) : "l"(den1_2));
    float den0 = d0l + d0h, den1 = d1l + d1h;
    den0 += __shfl_xor_sync(0xffffffffu, den0, 1);
    den0 += __shfl_xor_sync(0xffffffffu, den0, 2);
    den1 += __shfl_xor_sync(0xffffffffu, den1, 1);
    den1 += __shfl_xor_sync(0xffffffffu, den1, 2);
    if (qd == 0) {
        g_denp[sp][gr] = den0;
        g_denp[sp][gr + 8] = den1;
    }
#pragma unroll
    for (int n = 0; n < 8; n++) {
        float* o0 = &g_aggp[sp][(size_t)gr * 64 + n * 8 + c2];
        *(float2*)o0 = make_float2(Ot[n][0], Ot[n][1]);
        *(float2*)(o0 + 512) = make_float2(Ot[n][2], Ot[n][3]);
    }
}

// ---------------------------------------------------------------------------
// K3: combine 4 partials (float2 lanes); z = h + num/den ; LN ; head MLP.
__global__ __launch_bounds__(256) void k_epi(
    const float* __restrict__ sa, const float* __restrict__ lng, const float* __restrict__ lnb,
    const float* __restrict__ wa1, const float* __restrict__ ba1,
    const float* __restrict__ wa2, const float* __restrict__ ba2,
    float* __restrict__ out) {
    __shared__ float sAi[8][68];
    const int warp = threadIdx.x >> 5;
    const int lane = threadIdx.x & 31;
    const int row = blockIdx.x * 8 + warp;
    const int c = lane << 1;

    float den = 0.f;
    float nx = 0.f, ny = 0.f;
#pragma unroll
    for (int s = 0; s < SPLIT; s++) {
        den += g_denp[s][row];
        float2 t = *(const float2*)&g_aggp[s][row * 64 + c];
        nx += t.x; ny += t.y;
    }
    float invd = 1.0f / den;
    float2 h2 = *(const float2*)&g_h[row * 64 + c];
    float z0 = h2.x + nx * invd;
    float z1 = h2.y + ny * invd;
    float s = z0 + z1;
#pragma unroll
    for (int o = 16; o >= 1; o >>= 1) s += __shfl_xor_sync(0xffffffffu, s, o);
    float mu = s * (1.0f / 64.0f);
    float d0 = z0 - mu, d1 = z1 - mu;
    float v = d0 * d0 + d1 * d1;
#pragma unroll
    for (int o = 16; o >= 1; o >>= 1) v += __shfl_xor_sync(0xffffffffu, v, o);
    float inv = rsqrtf(v * (1.0f / 64.0f) + 1e-5f);
    float2 g2 = *(const float2*)&lng[c];
    float2 b2v = *(const float2*)&lnb[c];
    sAi[warp][c]     = fmaf(d0 * inv, g2.x, b2v.x);
    sAi[warp][c + 1] = fmaf(d1 * inv, g2.y, b2v.y);
    if (lane < 2) sAi[warp][64 + lane] = sa[row * 2 + lane];
    __syncwarp();

    float2 bb = *(const float2*)&ba1[c];
    float acc0 = bb.x, acc1 = bb.y;
#pragma unroll 11
    for (int i = 0; i < 66; i++) {
        float av = sAi[warp][i];
        float2 w = *(const float2*)&wa1[i * 64 + c];
        acc0 = fmaf(av, w.x, acc0);
        acc1 = fmaf(av, w.y, acc1);
    }
    acc0 = fmaxf(acc0, 0.0f);
    acc1 = fmaxf(acc1, 0.0f);
    float q0v = fmaf(acc0, wa2[c * 3 + 0], acc1 * wa2[c * 3 + 3]);
    float q1v = fmaf(acc0, wa2[c * 3 + 1], acc1 * wa2[c * 3 + 4]);
    float q2v = fmaf(acc0, wa2[c * 3 + 2], acc1 * wa2[c * 3 + 5]);
#pragma unroll
    for (int o = 16; o >= 1; o >>= 1) {
        q0v += __shfl_xor_sync(0xffffffffu, q0v, o);
        q1v += __shfl_xor_sync(0xffffffffu, q1v, o);
        q2v += __shfl_xor_sync(0xffffffffu, q2v, o);
    }
    if (lane == 0) {
        out[row * 3 + 0] = q0v + ba2[0];
        out[row * 3 + 1] = q1v + ba2[1];
        out[row * 3 + 2] = q2v + ba2[2];
    }
}

// ---------------------------------------------------------------------------
typedef CUresult (*PFN_tmEnc)(CUtensorMap*, CUtensorMapDataType, cuuint32_t, void*,
                              const cuuint64_t*, const cuuint64_t*, const cuuint32_t*,
                              const cuuint32_t*, CUtensorMapInterleave, CUtensorMapSwizzle,
                              CUtensorMapL2promotion, CUtensorMapFloatOOBfill);

extern "C" void kernel_launch(void* const* d_in, const int* in_sizes, int n_in,
                              void* d_out, int out_size) {
    const float* nf    = (const float*)d_in[0];
    const float* adj   = (const float*)d_in[1];
    const float* tc    = (const float*)d_in[2];
    const float* sa    = (const float*)d_in[3];
    const float* w1    = (const float*)d_in[4];
    const float* b1    = (const float*)d_in[5];
    const float* w2    = (const float*)d_in[6];
    const float* b2    = (const float*)d_in[7];
    const float* wq    = (const float*)d_in[8];
    const float* bq    = (const float*)d_in[9];
    const float* wk    = (const float*)d_in[10];
    const float* bk    = (const float*)d_in[11];
    const float* wg    = (const float*)d_in[12];
    const float* bg    = (const float*)d_in[13];
    const float* sbias = (const float*)d_in[14];
    const float* wm    = (const float*)d_in[15];
    const float* bm    = (const float*)d_in[16];
    const float* lng   = (const float*)d_in[17];
    const float* lnb   = (const float*)d_in[18];
    const float* wa1   = (const float*)d_in[19];
    const float* ba1   = (const float*)d_in[20];
    const float* wa2   = (const float*)d_in[21];
    const float* ba2   = (const float*)d_in[22];
    float* out = (float*)d_out;

    PFN_tmEnc fn = nullptr;
    cudaDriverEntryPointQueryResult st;
    cudaGetDriverEntryPoint("cuTensorMapEncodeTiled", (void**)&fn, cudaEnableDefault, &st);

    // adj tensormap: fp32 [8192, 8192], box [32, 128], SW128
    CUtensorMap tmA;
    {
        cuuint64_t dims[2] = {NN, NN};
        cuuint64_t strides[1] = {NN * 4ull};
        cuuint32_t box[2] = {32, 128};
        cuuint32_t es[2] = {1, 1};
        fn(&tmA, CU_TENSOR_MAP_DATA_TYPE_FLOAT32, 2, (void*)adj, dims, strides, box, es,
           CU_TENSOR_MAP_INTERLEAVE_NONE, CU_TENSOR_MAP_SWIZZLE_128B,
           CU_TENSOR_MAP_L2_PROMOTION_L2_128B, CU_TENSOR_MAP_FLOAT_OOB_FILL_NONE);
    }
    // K / V tensormaps: bf16 [64, 8192], box [64, 64], SW128
    CUtensorMap tmK, tmV;
    {
        void *kp = nullptr, *vp = nullptr;
        cudaGetSymbolAddress(&kp, g_kb);
        cudaGetSymbolAddress(&vp, g_mb);
        cuuint64_t dims[2] = {64, NN};
        cuuint64_t strides[1] = {128ull};
        cuuint32_t box[2] = {64, 64};
        cuuint32_t es[2] = {1, 1};
        fn(&tmK, CU_TENSOR_MAP_DATA_TYPE_BFLOAT16, 2, kp, dims, strides, box, es,
           CU_TENSOR_MAP_INTERLEAVE_NONE, CU_TENSOR_MAP_SWIZZLE_128B,
           CU_TENSOR_MAP_L2_PROMOTION_L2_128B, CU_TENSOR_MAP_FLOAT_OOB_FILL_NONE);
        fn(&tmV, CU_TENSOR_MAP_DATA_TYPE_BFLOAT16, 2, vp, dims, strides, box, es,
           CU_TENSOR_MAP_INTERLEAVE_NONE, CU_TENSOR_MAP_SWIZZLE_128B,
           CU_TENSOR_MAP_L2_PROMOTION_L2_128B, CU_TENSOR_MAP_FLOAT_OOB_FILL_NONE);
    }
    cudaFuncSetAttribute(k_attn, cudaFuncAttributeMaxDynamicSharedMemorySize, SMEM_SZ);
    cudaFuncSetAttribute(k_prep, cudaFuncAttributeMaxDynamicSharedMemorySize, PREP_SMEM);

    k_prep<<<512, 256, PREP_SMEM>>>(nf, tc, w1, b1, w2, b2, wq, bq, wk, bk, wm, bm, wg, bg);
    k_attn<<<256, 256, SMEM_SZ>>>(tmA, tmK, tmV, tc, sbias);
    k_epi<<<1024, 256>>>(sa, lng, lnb, wa1, ba1, wa2, ba2, out);
}

// round 13
// speedup vs baseline: 1.0878x; 1.0878x over previous
#include <cuda_runtime.h>
#include <cuda.h>
#include <cuda_bf16.h>

#define NN 8192
#define L2E 1.4426950408889634f
#define SPLIT 4
#define TILES 32

// smem layout (bytes) for k_attn
#define ADJ_OFF 0            // 2 x 32768
#define K_OFF   65536        // 2 x 8192
#define V_OFF   81920        // 2 x 8192
#define STK_OFF 98304        // 2 x 256
#define MB_OFF  98816        // 2 x 8
#define SMEM_SZ 98944

// k_prep dynamic smem: sA (8KB) + 3 x 16KB weight buffers
#define PREP_SMEM 57344

// Scratch (no allocation allowed)
__device__ float g_h[NN * 64];
__device__ float g_aggp[SPLIT][NN * 64];
__device__ float g_denp[SPLIT][NN];
__device__ __nv_bfloat16 g_qb[NN * 64];
__device__ __nv_bfloat16 g_kb[NN * 64];
__device__ __nv_bfloat16 g_mb[NN * 64];
__device__ float g_stk[NN];

// ---------------------------------------------------------------------------
__device__ __forceinline__ unsigned s2u(const void* p) {
    return (unsigned)__cvta_generic_to_shared(p);
}
__device__ __forceinline__ void cpa16(unsigned d, const void* s) {
    asm volatile("cp.async.cg.shared.global [%0],[%1],16;" :: "r"(d), "l"(s));
}
__device__ __forceinline__ void cpa4(unsigned d, const void* s) {
    asm volatile("cp.async.ca.shared.global [%0],[%1],4;" :: "r"(d), "l"(s));
}
__device__ __forceinline__ void cpcommit() { asm volatile("cp.async.commit_group;"); }
template <int N> __device__ __forceinline__ void cpwait() {
    asm volatile("cp.async.wait_group %0;" :: "n"(N));
}
__device__ __forceinline__ void mb_init(unsigned a, unsigned c) {
    asm volatile("mbarrier.init.shared.b64 [%0], %1;" :: "r"(a), "r"(c));
}
__device__ __forceinline__ void mb_exptx(unsigned a, unsigned b) {
    asm volatile("mbarrier.arrive.expect_tx.shared.b64 _, [%0], %1;" :: "r"(a), "r"(b) : "memory");
}
__device__ __forceinline__ void mb_wait(unsigned a, unsigned ph) {
    asm volatile(
        "{\n\t.reg .pred P;\n\t"
        "W%=:\n\t"
        "mbarrier.try_wait.parity.acquire.cta.shared::cta.b64 P, [%0], %1, 0x989680;\n\t"
        "@!P bra W%=;\n\t}"
        :: "r"(a), "r"(ph) : "memory");
}
__device__ __forceinline__ void tma2d(unsigned long long m, unsigned dst, int x, int y, unsigned mb) {
    asm volatile(
        "cp.async.bulk.tensor.2d.shared::cta.global.tile.mbarrier::complete_tx::bytes "
        "[%0], [%1, {%2, %3}], [%4];"
        :: "r"(dst), "l"(m), "r"(x), "r"(y), "r"(mb) : "memory");
}
__device__ __forceinline__ void ldm4(unsigned r[4], unsigned a) {
    asm volatile("ldmatrix.sync.aligned.m8n8.x4.shared.b16 {%0,%1,%2,%3}, [%4];"
                 : "=r"(r[0]), "=r"(r[1]), "=r"(r[2]), "=r"(r[3]) : "r"(a));
}
__device__ __forceinline__ void ldm4t(unsigned r[4], unsigned a) {
    asm volatile("ldmatrix.sync.aligned.m8n8.x4.trans.shared.b16 {%0,%1,%2,%3}, [%4];"
                 : "=r"(r[0]), "=r"(r[1]), "=r"(r[2]), "=r"(r[3]) : "r"(a));
}
__device__ __forceinline__ void mma16(float d[4], const unsigned a[4], unsigned b0, unsigned b1) {
    asm volatile("mma.sync.aligned.m16n8k16.row.col.f32.bf16.bf16.f32 "
                 "{%0,%1,%2,%3}, {%4,%5,%6,%7}, {%8,%9}, {%0,%1,%2,%3};"
                 : "+f"(d[0]), "+f"(d[1]), "+f"(d[2]), "+f"(d[3])
                 : "r"(a[0]), "r"(a[1]), "r"(a[2]), "r"(a[3]), "r"(b0), "r"(b1));
}
__device__ __forceinline__ unsigned long long pk2(float x) {
    unsigned long long r;
    asm("mov.b64 %0, {%1, %1};" : "=l"(r) : "f"(x));
    return r;
}

// Packed pair: P = adj * 2^(S + crow*st); accumulates packed den; returns bf16x2.
__device__ __forceinline__ unsigned pexp2(
    float s0, float s1, float stx, float sty, float crow, float a0, float a1,
    unsigned long long MAG2, unsigned long long NMAG2, unsigned long long NEG12,
    unsigned long long C4, unsigned long long C3, unsigned long long C2,
    unsigned long long C1, unsigned long long ONE2,
    unsigned long long& den2) {
    unsigned out;
    asm(
        "{\n\t"
        ".reg .b64 S2, st2, cr2, ad2, t2, rb2, r2, f2, p2, sc2;\n\t"
        ".reg .b32 il, ih;\n\t"
        ".reg .f32 sl, sh, pl, ph;\n\t"
        "mov.b64 S2, {%2, %3};\n\t"
        "mov.b64 st2, {%4, %5};\n\t"
        "mov.b64 cr2, {%6, %6};\n\t"
        "mov.b64 ad2, {%7, %8};\n\t"
        "fma.rn.f32x2 t2, cr2, st2, S2;\n\t"
        "add.rn.f32x2 rb2, t2, %9;\n\t"
        "add.rn.f32x2 r2, rb2, %10;\n\t"
        "fma.rn.f32x2 f2, r2, %11, t2;\n\t"
        "fma.rn.f32x2 p2, f2, %12, %13;\n\t"
        "fma.rn.f32x2 p2, f2, p2, %14;\n\t"
        "fma.rn.f32x2 p2, f2, p2, %15;\n\t"
        "fma.rn.f32x2 p2, f2, p2, %16;\n\t"
        "mov.b64 {il, ih}, rb2;\n\t"
        "shl.b32 il, il, 23;\n\t"
        "shl.b32 ih, ih, 23;\n\t"
        "add.s32 il, il, 0x3f800000;\n\t"
        "add.s32 ih, ih, 0x3f800000;\n\t"
        "mov.b32 sl, il;\n\t"
        "mov.b32 sh, ih;\n\t"
        "mov.b64 sc2, {sl, sh};\n\t"
        "mul.rn.f32x2 sc2, sc2, ad2;\n\t"
        "mul.rn.f32x2 p2, p2, sc2;\n\t"
        "add.rn.f32x2 %1, %1, p2;\n\t"
        "mov.b64 {pl, ph}, p2;\n\t"
        "cvt.rn.bf16x2.f32 %0, ph, pl;\n\t"
        "}"
        : "=r"(out), "+l"(den2)
        : "f"(s0), "f"(s1), "f"(stx), "f"(sty), "f"(crow), "f"(a0), "f"(a1),
          "l"(MAG2), "l"(NMAG2), "l"(NEG12), "l"(C4), "l"(C3), "l"(C2),
          "l"(C1), "l"(ONE2));
    return out;
}

// ---------------------------------------------------------------------------
__device__ __forceinline__ void store_bf16_row4(__nv_bfloat16* dst, const float* a, float s) {
    __nv_bfloat162 v01, v23;
    v01.x = __float2bfloat16(a[0] * s); v01.y = __float2bfloat16(a[1] * s);
    v23.x = __float2bfloat16(a[2] * s); v23.y = __float2bfloat16(a[3] * s);
    ((__nv_bfloat162*)dst)[0] = v01;
    ((__nv_bfloat162*)dst)[1] = v23;
}

// K1: BM=32, grid 256 (R10 shape — measured 17.4us). Fused q/k/m single pass;
// weights via cp.async overlapped with compute.
__global__ __launch_bounds__(256) void k_prep(
    const float* __restrict__ nf, const float* __restrict__ tc,
    const float* __restrict__ w1, const float* __restrict__ b1,
    const float* __restrict__ w2, const float* __restrict__ b2,
    const float* __restrict__ wq, const float* __restrict__ bq,
    const float* __restrict__ wk, const float* __restrict__ bk,
    const float* __restrict__ wm, const float* __restrict__ bm,
    const float* __restrict__ wg, const float* __restrict__ bg) {
    extern __shared__ __align__(16) float dsmf[];
    float* sA  = dsmf;          // 32x64
    float* sW0 = dsmf + 2048;   // w2, then wm
    float* sW1 = dsmf + 6144;   // wq
    float* sW2 = dsmf + 10240;  // wk
    __shared__ float sG[65];

    const int tid = threadIdx.x;
    const int r0 = (tid >> 4) << 1;
    const int c0 = (tid & 15) << 2;
    const int q0 = blockIdx.x * 32;
    const float tc0 = tc[0], tc1 = tc[1];

    // async weight prefetch: group A = w2 ; group B = wq, wk
    {
        unsigned d = s2u(sW0) + tid * 16;
        const char* s = (const char*)w2 + tid * 16;
#pragma unroll
        for (int i = 0; i < 4; i++) cpa16(d + i * 4096, s + i * 4096);
        cpcommit();
        unsigned d1 = s2u(sW1) + tid * 16;
        const char* s1 = (const char*)wq + tid * 16;
        unsigned d2 = s2u(sW2) + tid * 16;
        const char* s2 = (const char*)wk + tid * 16;
#pragma unroll
        for (int i = 0; i < 4; i++) { cpa16(d1 + i * 4096, s1 + i * 4096); cpa16(d2 + i * 4096, s2 + i * 4096); }
        cpcommit();
    }

    if (tid < 32) g_stk[q0 + tid] = nf[(q0 + tid) * 3 + 2];
    if (tid < 64) {
        float v = fmaf(tc0, wg[tid], fmaf(tc1, wg[64 + tid], bg[tid]));
        sG[tid] = 1.0f / (1.0f + __expf(-v));
    }

    // Stage 0: a = relu(x @ w1 + b1) -> sA
    float x0[2], x1[2], x2[2];
#pragma unroll
    for (int i = 0; i < 2; i++) {
        int row = q0 + r0 + i;
        x0[i] = nf[row * 3 + 0]; x1[i] = nf[row * 3 + 1]; x2[i] = nf[row * 3 + 2];
    }
#pragma unroll
    for (int c = 0; c < 4; c++) {
        int col = c0 + c;
        float wv0 = w1[col], wv1 = w1[64 + col], wv2 = w1[128 + col];
        float bb = fmaf(tc0, w1[192 + col], fmaf(tc1, w1[256 + col], b1[col]));
#pragma unroll
        for (int i = 0; i < 2; i++) {
            float a = fmaf(x0[i], wv0, fmaf(x1[i], wv1, fmaf(x2[i], wv2, bb)));
            sA[(r0 + i) * 64 + col] = fmaxf(a, 0.0f);
        }
    }
    cpwait<1>();          // w2 landed
    __syncthreads();
    if (tid == 0) {
        float s = 0.0f;
#pragma unroll 8
        for (int i = 0; i < 64; i++) s += sG[i];
        sG[64] = s * (1.0f / 64.0f) * 0.125f * L2E;   // gate/8 * log2e
    }

    // Stage 1: h = a @ w2 + b2
    float acc[2][4];
    {
        float4 bb = *(const float4*)&b2[c0];
#pragma unroll
        for (int i = 0; i < 2; i++) { acc[i][0] = bb.x; acc[i][1] = bb.y; acc[i][2] = bb.z; acc[i][3] = bb.w; }
#pragma unroll 8
        for (int j = 0; j < 64; j++) {
            float4 wv = *(const float4*)&sW0[j * 64 + c0];
#pragma unroll
            for (int i = 0; i < 2; i++) {
                float av = sA[(r0 + i) * 64 + j];
                acc[i][0] = fmaf(av, wv.x, acc[i][0]);
                acc[i][1] = fmaf(av, wv.y, acc[i][1]);
                acc[i][2] = fmaf(av, wv.z, acc[i][2]);
                acc[i][3] = fmaf(av, wv.w, acc[i][3]);
            }
        }
    }
    __syncthreads();      // all reads of sA / sW0 done

    // overwrite sA with h; prefetch wm into sW0
    {
        unsigned d = s2u(sW0) + tid * 16;
        const char* s = (const char*)wm + tid * 16;
#pragma unroll
        for (int i = 0; i < 4; i++) cpa16(d + i * 4096, s + i * 4096);
        cpcommit();
    }
#pragma unroll
    for (int i = 0; i < 2; i++) {
        float4 hv = make_float4(acc[i][0], acc[i][1], acc[i][2], acc[i][3]);
        *(float4*)&sA[(r0 + i) * 64 + c0] = hv;
        *(float4*)&g_h[(q0 + r0 + i) * 64 + c0] = hv;
    }
    cpwait<0>();          // wq, wk, wm all landed
    __syncthreads();

    // Stage 2: fused q/k/m GEMM — one pass over sA
    float aq[2][4], ak[2][4], am[2][4];
    {
        float4 bbq = *(const float4*)&bq[c0];
        float4 bbk = *(const float4*)&bk[c0];
        float4 bbm = *(const float4*)&bm[c0];
#pragma unroll
        for (int i = 0; i < 2; i++) {
            aq[i][0] = bbq.x; aq[i][1] = bbq.y; aq[i][2] = bbq.z; aq[i][3] = bbq.w;
            ak[i][0] = bbk.x; ak[i][1] = bbk.y; ak[i][2] = bbk.z; ak[i][3] = bbk.w;
            am[i][0] = bbm.x; am[i][1] = bbm.y; am[i][2] = bbm.z; am[i][3] = bbm.w;
        }
    }
#pragma unroll 4
    for (int j = 0; j < 64; j++) {
        float4 wvq = *(const float4*)&sW1[j * 64 + c0];
        float4 wvk = *(const float4*)&sW2[j * 64 + c0];
        float4 wvm = *(const float4*)&sW0[j * 64 + c0];
#pragma unroll
        for (int i = 0; i < 2; i++) {
            float av = sA[(r0 + i) * 64 + j];
            aq[i][0] = fmaf(av, wvq.x, aq[i][0]);
            aq[i][1] = fmaf(av, wvq.y, aq[i][1]);
            aq[i][2] = fmaf(av, wvq.z, aq[i][2]);
            aq[i][3] = fmaf(av, wvq.w, aq[i][3]);
            ak[i][0] = fmaf(av, wvk.x, ak[i][0]);
            ak[i][1] = fmaf(av, wvk.y, ak[i][1]);
            ak[i][2] = fmaf(av, wvk.z, ak[i][2]);
            ak[i][3] = fmaf(av, wvk.w, ak[i][3]);
            am[i][0] = fmaf(av, wvm.x, am[i][0]);
            am[i][1] = fmaf(av, wvm.y, am[i][1]);
            am[i][2] = fmaf(av, wvm.z, am[i][2]);
            am[i][3] = fmaf(av, wvm.w, am[i][3]);
        }
    }
    {
        float qs = sG[64];
#pragma unroll
        for (int i = 0; i < 2; i++) {
            store_bf16_row4(&g_qb[(q0 + r0 + i) * 64 + c0], aq[i], qs);
            store_bf16_row4(&g_kb[(q0 + r0 + i) * 64 + c0], ak[i], 1.0f);
            store_bf16_row4(&g_mb[(q0 + r0 + i) * 64 + c0], am[i], 1.0f);
        }
    }
}

// ---------------------------------------------------------------------------
// K2: flash attention. BM=128, BN=64, split-KV x4 (32 tiles). adj AND K/V via
// TMA on shared mbarriers; only stk on cp.async. Register-resident P.
__global__ __launch_bounds__(256) void k_attn(const __grid_constant__ CUtensorMap tmA,
                                              const __grid_constant__ CUtensorMap tmK,
                                              const __grid_constant__ CUtensorMap tmV,
                                              const float* __restrict__ tc,
                                              const float* __restrict__ sb) {
    extern __shared__ __align__(128) char dsm[];
    const unsigned su = s2u(dsm);
    const int tid = threadIdx.x;
    const int lane = tid & 31;
    const int wr = tid >> 5;
    const int r = lane >> 2;
    const int qd = lane & 3;
    const int c2 = qd << 1;
    const int qi = blockIdx.x >> 2;
    const int sp = blockIdx.x & 3;
    const int q0 = qi * 128;
    const int kvb = sp * 2048;
    const int gr = q0 + wr * 16 + r;
    const unsigned mbu = su + MB_OFF;

    if (tid == 0) { mb_init(mbu, 1); mb_init(mbu + 8, 1); }
    __syncthreads();

    const unsigned long long tA = (unsigned long long)&tmA;
    const unsigned long long tK = (unsigned long long)&tmK;
    const unsigned long long tV = (unsigned long long)&tmV;

#define ISSUE_TMA(T, B)                                                           \
    if (tid == 0) {                                                               \
        mb_exptx(mbu + 8 * (B), 49152);                                           \
        int x = kvb + (T) * 64;                                                   \
        tma2d(tA, su + ADJ_OFF + (B) * 32768,         x,      q0, mbu + 8 * (B)); \
        tma2d(tA, su + ADJ_OFF + (B) * 32768 + 16384, x + 32, q0, mbu + 8 * (B)); \
        tma2d(tK, su + K_OFF + (B) * 8192, 0, x, mbu + 8 * (B));                  \
        tma2d(tV, su + V_OFF + (B) * 8192, 0, x, mbu + 8 * (B));                  \
    }
#define STAGE_STK(T, B)                                                           \
    if (tid < 64) cpa4(su + STK_OFF + (B) * 256 + tid * 4, g_stk + kvb + (T) * 64 + tid);

    ISSUE_TMA(0, 0);
    ISSUE_TMA(1, 1);
    STAGE_STK(0, 0); cpcommit();
    STAGE_STK(1, 1); cpcommit();

    // Q fragments in registers
    unsigned qf[4][4];
#pragma unroll
    for (int kk = 0; kk < 4; kk++) {
        const __nv_bfloat16* qp = g_qb + (size_t)gr * 64 + kk * 16 + c2;
        qf[kk][0] = *(const unsigned*)qp;
        qf[kk][1] = *(const unsigned*)(qp + 512);
        qf[kk][2] = *(const unsigned*)(qp + 8);
        qf[kk][3] = *(const unsigned*)(qp + 520);
    }
    const float sbl = sb[0] * (1.0f - tc[0]) * L2E;
    const float crow0 = sbl * g_stk[gr];
    const float crow1 = sbl * g_stk[gr + 8];

    // packed constants (warp-uniform -> UR promotion)
    const unsigned long long MAG2 = pk2(12582912.0f);
    const unsigned long long NMAG2 = pk2(-12582912.0f);
    const unsigned long long NEG12 = pk2(-1.0f);
    const unsigned long long C4 = pk2(0.0096181291f);
    const unsigned long long C3 = pk2(0.0555041087f);
    const unsigned long long C2 = pk2(0.2402265070f);
    const unsigned long long C1 = pk2(0.6931471806f);
    const unsigned long long ONE2 = pk2(1.0f);

    // lane-constant smem addressing
    const unsigned swz = 16u * (lane & 7);
    const unsigned lrowK = (((lane >> 4) & 1) << 3) + (lane & 7);
    const unsigned lrowV = (((lane >> 3) & 1) << 3) + (lane & 7);
    const unsigned kc16 = ((lane >> 3) & 1) << 4;
    const unsigned vc16 = ((lane >> 4) & 1) << 4;
    unsigned kcol[4], vcol[4];
#pragma unroll
    for (int i = 0; i < 4; i++) {
        kcol[i] = ((unsigned)(i << 5) + kc16) ^ swz;
        vcol[i] = ((unsigned)(i << 5) + vc16) ^ swz;
    }
    const unsigned arow128 = (unsigned)(wr * 16 + r) << 7;
    const unsigned acb = 8u * qd;
    const unsigned aswz = 16u * r;

    float Ot[8][4];
#pragma unroll
    for (int n = 0; n < 8; n++) { Ot[n][0] = Ot[n][1] = Ot[n][2] = Ot[n][3] = 0.f; }
    unsigned long long den0_2 = 0ull, den1_2 = 0ull;

    for (int t = 0; t < TILES; t++) {
        const int b = t & 1;
        mb_wait(mbu + 8 * b, (t >> 1) & 1);
        cpwait<1>();
        __syncthreads();

        const unsigned kbase = su + K_OFF + b * 8192;
        const unsigned vbase = su + V_OFF + b * 8192;
        const char* adjb = dsm + b * 32768;
        const float* stkb = (const float*)(dsm + STK_OFF + b * 256);

        // S = Q @ K^T
        float S[8][4];
#pragma unroll
        for (int n = 0; n < 8; n++) { S[n][0] = S[n][1] = S[n][2] = S[n][3] = 0.f; }
#pragma unroll
        for (int jp = 0; jp < 4; jp++) {
            const unsigned rb = (unsigned)(16 * jp + lrowK) << 7;
#pragma unroll
            for (int kk = 0; kk < 4; kk++) {
                unsigned kf[4];
                ldm4(kf, kbase + rb + kcol[kk]);
                mma16(S[2 * jp],     qf[kk], kf[0], kf[1]);
                mma16(S[2 * jp + 1], qf[kk], kf[2], kf[3]);
            }
        }

        // interleaved pointwise + P@V, per k-chunk of 16 kv
#pragma unroll
        for (int kk = 0; kk < 4; kk++) {
            unsigned pa[4];
#pragma unroll
            for (int u = 0; u < 2; u++) {
                const int n = 2 * kk + u;
                float2 st = *(const float2*)(stkb + n * 8 + c2);
                unsigned ao = ((unsigned)(n >> 2) << 14) + arow128 +
                              ((acb + ((unsigned)(n & 3) << 5)) ^ aswz);
                float2 ad0 = *(const float2*)(adjb + ao);
                float2 ad1 = *(const float2*)(adjb + ao + 1024);
                pa[2 * u]     = pexp2(S[n][0], S[n][1], st.x, st.y, crow0, ad0.x, ad0.y,
                                      MAG2, NMAG2, NEG12, C4, C3, C2, C1, ONE2, den0_2);
                pa[2 * u + 1] = pexp2(S[n][2], S[n][3], st.x, st.y, crow1, ad1.x, ad1.y,
                                      MAG2, NMAG2, NEG12, C4, C3, C2, C1, ONE2, den1_2);
            }
#pragma unroll
            for (int dp = 0; dp < 4; dp++) {
                unsigned vf[4];
                ldm4t(vf, vbase + ((unsigned)(16 * kk + lrowV) << 7) + vcol[dp]);
                mma16(Ot[2 * dp],     pa, vf[0], vf[1]);
                mma16(Ot[2 * dp + 1], pa, vf[2], vf[3]);
            }
        }
        __syncthreads();

        if (t + 2 < TILES) {
            ISSUE_TMA(t + 2, b);
            STAGE_STK(t + 2, b);
        }
        cpcommit();
    }

    // unpack packed dens, reduce across quad, write partials
    float d0l, d0h, d1l, d1h;
    asm("mov.b64 {%0, %1}, %2;" : "=f"(d0l), "=f"(d0h) : "l"(den0_2));
    asm("mov.b64 {%0, %1}, %2;" : "=f"(d1l), "=f"(d1h) : "l"(den1_2));
    float den0 = d0l + d0h, den1 = d1l + d1h;
    den0 += __shfl_xor_sync(0xffffffffu, den0, 1);
    den0 += __shfl_xor_sync(0xffffffffu, den0, 2);
    den1 += __shfl_xor_sync(0xffffffffu, den1, 1);
    den1 += __shfl_xor_sync(0xffffffffu, den1, 2);
    if (qd == 0) {
        g_denp[sp][gr] = den0;
        g_denp[sp][gr + 8] = den1;
    }
#pragma unroll
    for (int n = 0; n < 8; n++) {
        float* o0 = &g_aggp[sp][(size_t)gr * 64 + n * 8 + c2];
        *(float2*)o0 = make_float2(Ot[n][0], Ot[n][1]);
        *(float2*)(o0 + 512) = make_float2(Ot[n][2], Ot[n][3]);
    }
}

// ---------------------------------------------------------------------------
// K3: combine 4 partials (float2 lanes); z = h + num/den ; LN ; head MLP.
__global__ __launch_bounds__(256) void k_epi(
    const float* __restrict__ sa, const float* __restrict__ lng, const float* __restrict__ lnb,
    const float* __restrict__ wa1, const float* __restrict__ ba1,
    const float* __restrict__ wa2, const float* __restrict__ ba2,
    float* __restrict__ out) {
    __shared__ float sAi[8][68];
    const int warp = threadIdx.x >> 5;
    const int lane = threadIdx.x & 31;
    const int row = blockIdx.x * 8 + warp;
    const int c = lane << 1;

    float den = 0.f;
    float nx = 0.f, ny = 0.f;
#pragma unroll
    for (int s = 0; s < SPLIT; s++) {
        den += g_denp[s][row];
        float2 t = *(const float2*)&g_aggp[s][row * 64 + c];
        nx += t.x; ny += t.y;
    }
    float invd = 1.0f / den;
    float2 h2 = *(const float2*)&g_h[row * 64 + c];
    float z0 = h2.x + nx * invd;
    float z1 = h2.y + ny * invd;
    float s = z0 + z1;
#pragma unroll
    for (int o = 16; o >= 1; o >>= 1) s += __shfl_xor_sync(0xffffffffu, s, o);
    float mu = s * (1.0f / 64.0f);
    float d0 = z0 - mu, d1 = z1 - mu;
    float v = d0 * d0 + d1 * d1;
#pragma unroll
    for (int o = 16; o >= 1; o >>= 1) v += __shfl_xor_sync(0xffffffffu, v, o);
    float inv = rsqrtf(v * (1.0f / 64.0f) + 1e-5f);
    float2 g2 = *(const float2*)&lng[c];
    float2 b2v = *(const float2*)&lnb[c];
    sAi[warp][c]     = fmaf(d0 * inv, g2.x, b2v.x);
    sAi[warp][c + 1] = fmaf(d1 * inv, g2.y, b2v.y);
    if (lane < 2) sAi[warp][64 + lane] = sa[row * 2 + lane];
    __syncwarp();

    float2 bb = *(const float2*)&ba1[c];
    float acc0 = bb.x, acc1 = bb.y;
#pragma unroll 11
    for (int i = 0; i < 66; i++) {
        float av = sAi[warp][i];
        float2 w = *(const float2*)&wa1[i * 64 + c];
        acc0 = fmaf(av, w.x, acc0);
        acc1 = fmaf(av, w.y, acc1);
    }
    acc0 = fmaxf(acc0, 0.0f);
    acc1 = fmaxf(acc1, 0.0f);
    float q0v = fmaf(acc0, wa2[c * 3 + 0], acc1 * wa2[c * 3 + 3]);
    float q1v = fmaf(acc0, wa2[c * 3 + 1], acc1 * wa2[c * 3 + 4]);
    float q2v = fmaf(acc0, wa2[c * 3 + 2], acc1 * wa2[c * 3 + 5]);
#pragma unroll
    for (int o = 16; o >= 1; o >>= 1) {
        q0v += __shfl_xor_sync(0xffffffffu, q0v, o);
        q1v += __shfl_xor_sync(0xffffffffu, q1v, o);
        q2v += __shfl_xor_sync(0xffffffffu, q2v, o);
    }
    if (lane == 0) {
        out[row * 3 + 0] = q0v + ba2[0];
        out[row * 3 + 1] = q1v + ba2[1];
        out[row * 3 + 2] = q2v + ba2[2];
    }
}

// ---------------------------------------------------------------------------
typedef CUresult (*PFN_tmEnc)(CUtensorMap*, CUtensorMapDataType, cuuint32_t, void*,
                              const cuuint64_t*, const cuuint64_t*, const cuuint32_t*,
                              const cuuint32_t*, CUtensorMapInterleave, CUtensorMapSwizzle,
                              CUtensorMapL2promotion, CUtensorMapFloatOOBfill);

extern "C" void kernel_launch(void* const* d_in, const int* in_sizes, int n_in,
                              void* d_out, int out_size) {
    const float* nf    = (const float*)d_in[0];
    const float* adj   = (const float*)d_in[1];
    const float* tc    = (const float*)d_in[2];
    const float* sa    = (const float*)d_in[3];
    const float* w1    = (const float*)d_in[4];
    const float* b1    = (const float*)d_in[5];
    const float* w2    = (const float*)d_in[6];
    const float* b2    = (const float*)d_in[7];
    const float* wq    = (const float*)d_in[8];
    const float* bq    = (const float*)d_in[9];
    const float* wk    = (const float*)d_in[10];
    const float* bk    = (const float*)d_in[11];
    const float* wg    = (const float*)d_in[12];
    const float* bg    = (const float*)d_in[13];
    const float* sbias = (const float*)d_in[14];
    const float* wm    = (const float*)d_in[15];
    const float* bm    = (const float*)d_in[16];
    const float* lng   = (const float*)d_in[17];
    const float* lnb   = (const float*)d_in[18];
    const float* wa1   = (const float*)d_in[19];
    const float* ba1   = (const float*)d_in[20];
    const float* wa2   = (const float*)d_in[21];
    const float* ba2   = (const float*)d_in[22];
    float* out = (float*)d_out;

    PFN_tmEnc fn = nullptr;
    cudaDriverEntryPointQueryResult st;
    cudaGetDriverEntryPoint("cuTensorMapEncodeTiled", (void**)&fn, cudaEnableDefault, &st);

    // adj tensormap: fp32 [8192, 8192], box [32, 128], SW128
    CUtensorMap tmA;
    {
        cuuint64_t dims[2] = {NN, NN};
        cuuint64_t strides[1] = {NN * 4ull};
        cuuint32_t box[2] = {32, 128};
        cuuint32_t es[2] = {1, 1};
        fn(&tmA, CU_TENSOR_MAP_DATA_TYPE_FLOAT32, 2, (void*)adj, dims, strides, box, es,
           CU_TENSOR_MAP_INTERLEAVE_NONE, CU_TENSOR_MAP_SWIZZLE_128B,
           CU_TENSOR_MAP_L2_PROMOTION_L2_128B, CU_TENSOR_MAP_FLOAT_OOB_FILL_NONE);
    }
    // K / V tensormaps: bf16 [64, 8192], box [64, 64], SW128
    CUtensorMap tmK, tmV;
    {
        void *kp = nullptr, *vp = nullptr;
        cudaGetSymbolAddress(&kp, g_kb);
        cudaGetSymbolAddress(&vp, g_mb);
        cuuint64_t dims[2] = {64, NN};
        cuuint64_t strides[1] = {128ull};
        cuuint32_t box[2] = {64, 64};
        cuuint32_t es[2] = {1, 1};
        fn(&tmK, CU_TENSOR_MAP_DATA_TYPE_BFLOAT16, 2, kp, dims, strides, box, es,
           CU_TENSOR_MAP_INTERLEAVE_NONE, CU_TENSOR_MAP_SWIZZLE_128B,
           CU_TENSOR_MAP_L2_PROMOTION_L2_128B, CU_TENSOR_MAP_FLOAT_OOB_FILL_NONE);
        fn(&tmV, CU_TENSOR_MAP_DATA_TYPE_BFLOAT16, 2, vp, dims, strides, box, es,
           CU_TENSOR_MAP_INTERLEAVE_NONE, CU_TENSOR_MAP_SWIZZLE_128B,
           CU_TENSOR_MAP_L2_PROMOTION_L2_128B, CU_TENSOR_MAP_FLOAT_OOB_FILL_NONE);
    }
    cudaFuncSetAttribute(k_attn, cudaFuncAttributeMaxDynamicSharedMemorySize, SMEM_SZ);
    cudaFuncSetAttribute(k_prep, cudaFuncAttributeMaxDynamicSharedMemorySize, PREP_SMEM);

    k_prep<<<256, 256, PREP_SMEM>>>(nf, tc, w1, b1, w2, b2, wq, bq, wk, bk, wm, bm, wg, bg);
    k_attn<<<256, 256, SMEM_SZ>>>(tmA, tmK, tmV, tc, sbias);
    k_epi<<<1024, 256>>>(sa, lng, lnb, wa1, ba1, wa2, ba2, out);
}